// round 10
// baseline (speedup 1.0000x reference)
#include <cuda_runtime.h>

#define B_   2
#define NT_  1024
#define ND_  512
#define NH_  196
#define HP_  256      // padded hidden dim (zeros for h >= 196)
#define KL_  128

// scratch (device globals: allocation-free)
__device__ float g_wj[B_ * 8 * HP_];    // per-j weights: [w_xn, M1x(3), w_vn, M1v(3)]
__device__ float g_wc[B_ * 10 * HP_];   // per-i weights: [w_N, w_x0n, M0x(3), w_vbn, M0v(3), b0]

typedef unsigned long long u64t;

__device__ __forceinline__ u64t pack2(float x, float y) {
    u64t r; asm("mov.b64 %0, {%1, %2};" : "=l"(r) : "f"(x), "f"(y)); return r;
}
__device__ __forceinline__ float2 unpack2(u64t v) {
    float2 r; asm("mov.b64 {%0, %1}, %2;" : "=f"(r.x), "=f"(r.y) : "l"(v)); return r;
}
__device__ __forceinline__ u64t ffma2(u64t a, u64t b, u64t c) {
    u64t d; asm("fma.rn.f32x2 %0, %1, %2, %3;" : "=l"(d) : "l"(a), "l"(b), "l"(c)); return d;
}
__device__ __forceinline__ u64t add2(u64t a, u64t b) {
    u64t d; asm("add.rn.f32x2 %0, %1, %2;" : "=l"(d) : "l"(a), "l"(b)); return d;
}

// ---------------------------------------------------------------------------
// Kernel 1: fold basis into W0 rows (tiny)
// ---------------------------------------------------------------------------
__global__ void precomp_kernel(const float* __restrict__ W0,
                               const float* __restrict__ b0,
                               const float* __restrict__ basis) {
    int b = blockIdx.x, h = threadIdx.x;
    float* wj = g_wj + b * 8 * HP_;
    float* wc = g_wc + b * 10 * HP_;
    if (h >= NH_) {
        for (int r = 0; r < 8;  r++) wj[r * HP_ + h] = 0.f;
        for (int r = 0; r < 10; r++) wc[r * HP_ + h] = 0.f;
        return;
    }
    const float* bs = basis + b * 6 * 3;
    wj[0 * HP_ + h] = W0[15 * NH_ + h];   // |x|
    wj[4 * HP_ + h] = W0[22 * NH_ + h];   // |vc|
    wc[0 * HP_ + h] = W0[0 * NH_ + h];    // N
    wc[1 * HP_ + h] = W0[1 * NH_ + h];    // |x0|
    wc[5 * HP_ + h] = W0[8 * NH_ + h];    // |vbulk|
    wc[9 * HP_ + h] = b0[h];
    for (int d = 0; d < 3; d++) {
        float m0x = 0.f, m0v = 0.f, m1 = 0.f, m2 = 0.f;
        for (int k = 0; k < 6; k++) {
            float bb = bs[k * 3 + d];
            m0x += bb * W0[(2  + k) * NH_ + h];
            m0v += bb * W0[(9  + k) * NH_ + h];
            m1  += bb * W0[(16 + k) * NH_ + h];
            m2  += bb * W0[(23 + k) * NH_ + h];
        }
        wj[(1 + d) * HP_ + h] = m1;
        wj[(5 + d) * HP_ + h] = m2;
        wc[(2 + d) * HP_ + h] = m0x;
        wc[(6 + d) * HP_ + h] = m0v;
    }
}

// ---------------------------------------------------------------------------
// Kernel 2: proven R1/R5 structure (phases 1-3 untouched) + fused MLP tail
// as phase 4. One CTA per (b,i), 128 threads.
// ---------------------------------------------------------------------------
__global__ __launch_bounds__(128) void main_kernel(
    const float* __restrict__ x0g, const float* __restrict__ xg,
    const float* __restrict__ Ng,  const float* __restrict__ vg,
    const float* __restrict__ W1,  const float* __restrict__ b1,
    const float* __restrict__ W2,  const float* __restrict__ b2,
    float* __restrict__ out) {
    __shared__ float4 ftr4[8 * 128];           // features transposed: ftr[f][512]
    float* ftr = (float*)ftr4;
    __shared__ float red[32];
    __shared__ float hms[NH_];                 // pooled hidden row
    __shared__ float h2s[NH_];                 // after layer 1

    int t = threadIdx.x;
    int blk = blockIdx.x;
    int b = blk >> 10, i = blk & (NT_ - 1);
    int lane = t & 31, w = t >> 5;
    int base = (b * NT_ + i) * ND_ * 3;

    // --- phase 1: vbulk (keep v in regs for phase 2) ---
    float vxr[4], vyr[4], vzr[4];
    float s0 = 0.f, s1 = 0.f, s2 = 0.f;
#pragma unroll
    for (int r = 0; r < 4; r++) {
        int j = t + r * 128;
        const float* vp = vg + base + j * 3;
        float a = vp[0], bb = vp[1], c = vp[2];
        vxr[r] = a; vyr[r] = bb; vzr[r] = c;
        s0 += a; s1 += bb; s2 += c;
    }
#pragma unroll
    for (int off = 16; off; off >>= 1) {
        s0 += __shfl_xor_sync(0xffffffffu, s0, off);
        s1 += __shfl_xor_sync(0xffffffffu, s1, off);
        s2 += __shfl_xor_sync(0xffffffffu, s2, off);
    }
    if (lane == 0) { red[w * 8 + 0] = s0; red[w * 8 + 1] = s1; red[w * 8 + 2] = s2; }
    __syncthreads();
    float vb0 = (red[0] + red[8]  + red[16] + red[24]) * (1.f / ND_);
    float vb1 = (red[1] + red[9]  + red[17] + red[25]) * (1.f / ND_);
    float vb2 = (red[2] + red[10] + red[18] + red[26]) * (1.f / ND_);
    __syncthreads();

    // --- phase 2: stage per-j features + per-feature sums ---
    float fs[8] = {0.f, 0.f, 0.f, 0.f, 0.f, 0.f, 0.f, 0.f};
#pragma unroll
    for (int r = 0; r < 4; r++) {
        int j = t + r * 128;
        const float* xp = xg + base + j * 3;
        float a = xp[0], bb = xp[1], c = xp[2];
        float d  = a * a + bb * bb + c * c;
        float ri = rsqrtf(d);
        float n  = d * ri;
        float e1 = a * ri, e2 = bb * ri, e3 = c * ri;
        ftr[0 * 512 + j] = n;  ftr[1 * 512 + j] = e1;
        ftr[2 * 512 + j] = e2; ftr[3 * 512 + j] = e3;
        fs[0] += n; fs[1] += e1; fs[2] += e2; fs[3] += e3;
        float c0 = vxr[r] - vb0, c1 = vyr[r] - vb1, c2 = vzr[r] - vb2;
        d  = c0 * c0 + c1 * c1 + c2 * c2;
        ri = rsqrtf(d);
        n  = d * ri;
        e1 = c0 * ri; e2 = c1 * ri; e3 = c2 * ri;
        ftr[4 * 512 + j] = n;  ftr[5 * 512 + j] = e1;
        ftr[6 * 512 + j] = e2; ftr[7 * 512 + j] = e3;
        fs[4] += n; fs[5] += e1; fs[6] += e2; fs[7] += e3;
    }
#pragma unroll
    for (int off = 16; off; off >>= 1)
#pragma unroll
        for (int f = 0; f < 8; f++) fs[f] += __shfl_xor_sync(0xffffffffu, fs[f], off);
    if (lane == 0) {
#pragma unroll
        for (int f = 0; f < 8; f++) red[w * 8 + f] = fs[f];
    }
    __syncthreads();
    float fm[8];
#pragma unroll
    for (int f = 0; f < 8; f++)
        fm[f] = (red[f] + red[8 + f] + red[16 + f] + red[24 + f]) * (1.f / ND_);

    // --- per-i constant C (cheap, redundant per thread) ---
    float Nv = Ng[b * NT_ + i];
    const float* x0p = x0g + (b * NT_ + i) * 3;
    float p0 = x0p[0], p1 = x0p[1], p2 = x0p[2];
    float d0 = p0 * p0 + p1 * p1 + p2 * p2;
    float ri0 = rsqrtf(d0);
    float x0n = d0 * ri0;
    float u0 = p0 * ri0, u1 = p1 * ri0, u2 = p2 * ri0;
    float dv = vb0 * vb0 + vb1 * vb1 + vb2 * vb2;
    float riv = rsqrtf(dv);
    float vbn = dv * riv;
    float q0 = vb0 * riv, q1 = vb1 * riv, q2 = vb2 * riv;

    const float* wj = g_wj + b * 8 * HP_;
    const float* wc = g_wc + b * 10 * HP_;
    int h0 = t, h1i = t + 128;

    float C0, C1;
    {
        float c;
        c  = wc[9 * HP_ + h0];
        c += Nv  * wc[0 * HP_ + h0];
        c += x0n * wc[1 * HP_ + h0];
        c += u0 * wc[2 * HP_ + h0] + u1 * wc[3 * HP_ + h0] + u2 * wc[4 * HP_ + h0];
        c += vbn * wc[5 * HP_ + h0];
        c += q0 * wc[6 * HP_ + h0] + q1 * wc[7 * HP_ + h0] + q2 * wc[8 * HP_ + h0];
        C0 = c;
        c  = wc[9 * HP_ + h1i];
        c += Nv  * wc[0 * HP_ + h1i];
        c += x0n * wc[1 * HP_ + h1i];
        c += u0 * wc[2 * HP_ + h1i] + u1 * wc[3 * HP_ + h1i] + u2 * wc[4 * HP_ + h1i];
        c += vbn * wc[5 * HP_ + h1i];
        c += q0 * wc[6 * HP_ + h1i] + q1 * wc[7 * HP_ + h1i] + q2 * wc[8 * HP_ + h1i];
        C1 = c;
    }

    float w0s[8], w1s[8];
    u64t  w0p[8], w1p[8];
#pragma unroll
    for (int f = 0; f < 8; f++) {
        w0s[f] = wj[f * HP_ + h0];
        w1s[f] = wj[f * HP_ + h1i];
        w0p[f] = pack2(w0s[f], w0s[f]);
        w1p[f] = pack2(w1s[f], w1s[f]);
    }
    u64t C0p = pack2(C0, C0), C1p = pack2(C1, C1);

    // --- phase 3: hot loop. acc = sum_j |pre_j| for 2 h's, f32x2 over j ---
    const u64t MASK = 0x7FFFFFFF7FFFFFFFULL;
    u64t acc0 = 0ull, acc1 = 0ull;
#pragma unroll 1
    for (int j4 = 0; j4 < 512; j4 += 4) {
        ulonglong2 qq[8];
#pragma unroll
        for (int f = 0; f < 8; f++)
            qq[f] = *(const ulonglong2*)(ftr + f * 512 + j4);
        u64t p;
        p = C0p;
#pragma unroll
        for (int f = 0; f < 8; f++) p = ffma2(qq[f].x, w0p[f], p);
        acc0 = add2(acc0, p & MASK);
        p = C0p;
#pragma unroll
        for (int f = 0; f < 8; f++) p = ffma2(qq[f].y, w0p[f], p);
        acc0 = add2(acc0, p & MASK);
        p = C1p;
#pragma unroll
        for (int f = 0; f < 8; f++) p = ffma2(qq[f].x, w1p[f], p);
        acc1 = add2(acc1, p & MASK);
        p = C1p;
#pragma unroll
        for (int f = 0; f < 8; f++) p = ffma2(qq[f].y, w1p[f], p);
        acc1 = add2(acc1, p & MASK);
    }

    // mean(leaky) = 0.505*mean(pre) + 0.495*mean|pre|; mean(pre) is analytic
    float S0 = C0, S1 = C1;
#pragma unroll
    for (int f = 0; f < 8; f++) { S0 += fm[f] * w0s[f]; S1 += fm[f] * w1s[f]; }
    float2 e0 = unpack2(acc0), e1 = unpack2(acc1);
    float hm0 = 0.505f * S0 + (0.495f / ND_) * (e0.x + e0.y);
    float hm1 = 0.505f * S1 + (0.495f / ND_) * (e1.x + e1.y);

    hms[h0] = hm0;
    if (h1i < NH_) hms[h1i] = hm1;
    __syncthreads();

    // --- phase 4a: layer 1 — thread t owns cols (t, t+128); coalesced W1 LDG ---
    {
        int c1 = (h1i < NH_) ? h1i : (NH_ - 1);
        float a0 = b1[h0],  a1 = b1[c1];
        float a0b = 0.f,    a1b = 0.f;
#pragma unroll 1
        for (int k = 0; k < 196; k += 4) {
            float hv0 = hms[k], hv1 = hms[k + 1], hv2 = hms[k + 2], hv3 = hms[k + 3];
            const float* Wk = W1 + k * NH_;
            float wa0 = Wk[h0],            wa1 = Wk[NH_ + h0];
            float wa2 = Wk[2 * NH_ + h0],  wa3 = Wk[3 * NH_ + h0];
            float wb0 = Wk[c1],            wb1 = Wk[NH_ + c1];
            float wb2 = Wk[2 * NH_ + c1],  wb3 = Wk[3 * NH_ + c1];
            a0  = fmaf(hv0, wa0, a0);  a0b = fmaf(hv1, wa1, a0b);
            a0  = fmaf(hv2, wa2, a0);  a0b = fmaf(hv3, wa3, a0b);
            a1  = fmaf(hv0, wb0, a1);  a1b = fmaf(hv1, wb1, a1b);
            a1  = fmaf(hv2, wb2, a1);  a1b = fmaf(hv3, wb3, a1b);
        }
        float z0 = a0 + a0b, z1 = a1 + a1b;
        h2s[h0] = fmaxf(z0, 0.01f * z0);
        if (h1i < NH_) h2s[h1i] = fmaxf(z1, 0.01f * z1);
    }
    __syncthreads();

    // --- phase 4b: layer 2 — thread t owns output o = t (128 outputs) ---
    {
        int o = t;
        float a0 = b2[o], a0b = 0.f;
#pragma unroll 1
        for (int k = 0; k < 196; k += 4) {
            float hv0 = h2s[k], hv1 = h2s[k + 1], hv2 = h2s[k + 2], hv3 = h2s[k + 3];
            const float* Wk = W2 + k * KL_;
            float w0v = Wk[o],            w1v = Wk[KL_ + o];
            float w2v = Wk[2 * KL_ + o],  w3v = Wk[3 * KL_ + o];
            a0  = fmaf(hv0, w0v, a0);  a0b = fmaf(hv1, w1v, a0b);
            a0  = fmaf(hv2, w2v, a0);  a0b = fmaf(hv3, w3v, a0b);
        }
        out[blk * KL_ + o] = a0 + a0b;
    }
}

// ---------------------------------------------------------------------------
extern "C" void kernel_launch(void* const* d_in, const int* in_sizes, int n_in,
                              void* d_out, int out_size) {
    const float* x0    = (const float*)d_in[0];
    const float* x     = (const float*)d_in[1];
    const float* N     = (const float*)d_in[2];
    const float* basis = (const float*)d_in[3];
    const float* v     = (const float*)d_in[4];
    const float* W0    = (const float*)d_in[5];
    const float* b0    = (const float*)d_in[6];
    const float* W1    = (const float*)d_in[7];
    const float* b1    = (const float*)d_in[8];
    const float* W2    = (const float*)d_in[9];
    const float* b2    = (const float*)d_in[10];

    precomp_kernel<<<B_, HP_>>>(W0, b0, basis);
    main_kernel<<<B_ * NT_, 128>>>(x0, x, N, v, W1, b1, W2, b2, (float*)d_out);
}

// round 11
// speedup vs baseline: 1.0166x; 1.0166x over previous
#include <cuda_runtime.h>

#define B_   2
#define NT_  1024
#define ND_  512
#define NH_  196
#define HP_  256      // padded hidden dim (zeros for h >= 196)
#define KL_  128
#define RT_  4        // tail rows per CTA

// scratch (device globals: allocation-free)
__device__ float g_wj[B_ * 8 * HP_];
__device__ float g_wc[B_ * 10 * HP_];
__device__ float g_hm[B_ * NT_ * NH_];

typedef unsigned long long u64t;

__device__ __forceinline__ u64t pack2(float x, float y) {
    u64t r; asm("mov.b64 %0, {%1, %2};" : "=l"(r) : "f"(x), "f"(y)); return r;
}
__device__ __forceinline__ float2 unpack2(u64t v) {
    float2 r; asm("mov.b64 {%0, %1}, %2;" : "=f"(r.x), "=f"(r.y) : "l"(v)); return r;
}
__device__ __forceinline__ u64t ffma2(u64t a, u64t b, u64t c) {
    u64t d; asm("fma.rn.f32x2 %0, %1, %2, %3;" : "=l"(d) : "l"(a), "l"(b), "l"(c)); return d;
}
__device__ __forceinline__ u64t add2(u64t a, u64t b) {
    u64t d; asm("add.rn.f32x2 %0, %1, %2;" : "=l"(d) : "l"(a), "l"(b)); return d;
}

// ---------------------------------------------------------------------------
// Kernel 1: fold basis into W0 rows (tiny)
// ---------------------------------------------------------------------------
__global__ void precomp_kernel(const float* __restrict__ W0,
                               const float* __restrict__ b0,
                               const float* __restrict__ basis) {
    int b = blockIdx.x, h = threadIdx.x;
    float* wj = g_wj + b * 8 * HP_;
    float* wc = g_wc + b * 10 * HP_;
    if (h >= NH_) {
        for (int r = 0; r < 8;  r++) wj[r * HP_ + h] = 0.f;
        for (int r = 0; r < 10; r++) wc[r * HP_ + h] = 0.f;
        return;
    }
    const float* bs = basis + b * 6 * 3;
    wj[0 * HP_ + h] = W0[15 * NH_ + h];
    wj[4 * HP_ + h] = W0[22 * NH_ + h];
    wc[0 * HP_ + h] = W0[0 * NH_ + h];
    wc[1 * HP_ + h] = W0[1 * NH_ + h];
    wc[5 * HP_ + h] = W0[8 * NH_ + h];
    wc[9 * HP_ + h] = b0[h];
    for (int d = 0; d < 3; d++) {
        float m0x = 0.f, m0v = 0.f, m1 = 0.f, m2 = 0.f;
        for (int k = 0; k < 6; k++) {
            float bb = bs[k * 3 + d];
            m0x += bb * W0[(2  + k) * NH_ + h];
            m0v += bb * W0[(9  + k) * NH_ + h];
            m1  += bb * W0[(16 + k) * NH_ + h];
            m2  += bb * W0[(23 + k) * NH_ + h];
        }
        wj[(1 + d) * HP_ + h] = m1;
        wj[(5 + d) * HP_ + h] = m2;
        wc[(2 + d) * HP_ + h] = m0x;
        wc[(6 + d) * HP_ + h] = m0v;
    }
}

// ---------------------------------------------------------------------------
// Kernel 2: proven structure; phase 3 now warp-specialized: warps 0-2 run the
// 2-h loop, warp 3 (whose h1 range 224-255 is all padding) runs a 1-h loop.
// ---------------------------------------------------------------------------
__global__ __launch_bounds__(128) void main_kernel(
    const float* __restrict__ x0g, const float* __restrict__ xg,
    const float* __restrict__ Ng,  const float* __restrict__ vg) {
    __shared__ float4 ftr4[8 * 128];
    float* ftr = (float*)ftr4;
    __shared__ float red[32];

    int t = threadIdx.x;
    int blk = blockIdx.x;
    int b = blk >> 10, i = blk & (NT_ - 1);
    int lane = t & 31, w = t >> 5;
    int base = (b * NT_ + i) * ND_ * 3;

    // --- phase 1: vbulk ---
    float vxr[4], vyr[4], vzr[4];
    float s0 = 0.f, s1 = 0.f, s2 = 0.f;
#pragma unroll
    for (int r = 0; r < 4; r++) {
        int j = t + r * 128;
        const float* vp = vg + base + j * 3;
        float a = vp[0], bb = vp[1], c = vp[2];
        vxr[r] = a; vyr[r] = bb; vzr[r] = c;
        s0 += a; s1 += bb; s2 += c;
    }
#pragma unroll
    for (int off = 16; off; off >>= 1) {
        s0 += __shfl_xor_sync(0xffffffffu, s0, off);
        s1 += __shfl_xor_sync(0xffffffffu, s1, off);
        s2 += __shfl_xor_sync(0xffffffffu, s2, off);
    }
    if (lane == 0) { red[w * 8 + 0] = s0; red[w * 8 + 1] = s1; red[w * 8 + 2] = s2; }
    __syncthreads();
    float vb0 = (red[0] + red[8]  + red[16] + red[24]) * (1.f / ND_);
    float vb1 = (red[1] + red[9]  + red[17] + red[25]) * (1.f / ND_);
    float vb2 = (red[2] + red[10] + red[18] + red[26]) * (1.f / ND_);
    __syncthreads();

    // --- phase 2: features + per-feature sums ---
    float fs[8] = {0.f, 0.f, 0.f, 0.f, 0.f, 0.f, 0.f, 0.f};
#pragma unroll
    for (int r = 0; r < 4; r++) {
        int j = t + r * 128;
        const float* xp = xg + base + j * 3;
        float a = xp[0], bb = xp[1], c = xp[2];
        float d  = a * a + bb * bb + c * c;
        float ri = rsqrtf(d);
        float n  = d * ri;
        float e1 = a * ri, e2 = bb * ri, e3 = c * ri;
        ftr[0 * 512 + j] = n;  ftr[1 * 512 + j] = e1;
        ftr[2 * 512 + j] = e2; ftr[3 * 512 + j] = e3;
        fs[0] += n; fs[1] += e1; fs[2] += e2; fs[3] += e3;
        float c0 = vxr[r] - vb0, c1 = vyr[r] - vb1, c2 = vzr[r] - vb2;
        d  = c0 * c0 + c1 * c1 + c2 * c2;
        ri = rsqrtf(d);
        n  = d * ri;
        e1 = c0 * ri; e2 = c1 * ri; e3 = c2 * ri;
        ftr[4 * 512 + j] = n;  ftr[5 * 512 + j] = e1;
        ftr[6 * 512 + j] = e2; ftr[7 * 512 + j] = e3;
        fs[4] += n; fs[5] += e1; fs[6] += e2; fs[7] += e3;
    }
#pragma unroll
    for (int off = 16; off; off >>= 1)
#pragma unroll
        for (int f = 0; f < 8; f++) fs[f] += __shfl_xor_sync(0xffffffffu, fs[f], off);
    if (lane == 0) {
#pragma unroll
        for (int f = 0; f < 8; f++) red[w * 8 + f] = fs[f];
    }
    __syncthreads();
    float fm[8];
#pragma unroll
    for (int f = 0; f < 8; f++)
        fm[f] = (red[f] + red[8 + f] + red[16 + f] + red[24 + f]) * (1.f / ND_);

    // --- per-i constant C ---
    float Nv = Ng[b * NT_ + i];
    const float* x0p = x0g + (b * NT_ + i) * 3;
    float p0 = x0p[0], p1 = x0p[1], p2 = x0p[2];
    float d0 = p0 * p0 + p1 * p1 + p2 * p2;
    float ri0 = rsqrtf(d0);
    float x0n = d0 * ri0;
    float u0 = p0 * ri0, u1 = p1 * ri0, u2 = p2 * ri0;
    float dv = vb0 * vb0 + vb1 * vb1 + vb2 * vb2;
    float riv = rsqrtf(dv);
    float vbn = dv * riv;
    float q0 = vb0 * riv, q1 = vb1 * riv, q2 = vb2 * riv;

    const float* wj = g_wj + b * 8 * HP_;
    const float* wc = g_wc + b * 10 * HP_;
    int h0 = t, h1i = t + 128;

    float C0, C1;
    {
        float c;
        c  = wc[9 * HP_ + h0];
        c += Nv  * wc[0 * HP_ + h0];
        c += x0n * wc[1 * HP_ + h0];
        c += u0 * wc[2 * HP_ + h0] + u1 * wc[3 * HP_ + h0] + u2 * wc[4 * HP_ + h0];
        c += vbn * wc[5 * HP_ + h0];
        c += q0 * wc[6 * HP_ + h0] + q1 * wc[7 * HP_ + h0] + q2 * wc[8 * HP_ + h0];
        C0 = c;
        c  = wc[9 * HP_ + h1i];
        c += Nv  * wc[0 * HP_ + h1i];
        c += x0n * wc[1 * HP_ + h1i];
        c += u0 * wc[2 * HP_ + h1i] + u1 * wc[3 * HP_ + h1i] + u2 * wc[4 * HP_ + h1i];
        c += vbn * wc[5 * HP_ + h1i];
        c += q0 * wc[6 * HP_ + h1i] + q1 * wc[7 * HP_ + h1i] + q2 * wc[8 * HP_ + h1i];
        C1 = c;
    }

    float w0s[8], w1s[8];
    u64t  w0p[8], w1p[8];
#pragma unroll
    for (int f = 0; f < 8; f++) {
        w0s[f] = wj[f * HP_ + h0];
        w1s[f] = wj[f * HP_ + h1i];
        w0p[f] = pack2(w0s[f], w0s[f]);
        w1p[f] = pack2(w1s[f], w1s[f]);
    }
    u64t C0p = pack2(C0, C0), C1p = pack2(C1, C1);

    // --- phase 3: hot loop (warp-specialized) ---
    const u64t MASK = 0x7FFFFFFF7FFFFFFFULL;
    u64t acc0 = 0ull, acc1 = 0ull;
    if (w < 3) {
#pragma unroll 1
        for (int j4 = 0; j4 < 512; j4 += 4) {
            ulonglong2 qq[8];
#pragma unroll
            for (int f = 0; f < 8; f++)
                qq[f] = *(const ulonglong2*)(ftr + f * 512 + j4);
            u64t p;
            p = C0p;
#pragma unroll
            for (int f = 0; f < 8; f++) p = ffma2(qq[f].x, w0p[f], p);
            acc0 = add2(acc0, p & MASK);
            p = C0p;
#pragma unroll
            for (int f = 0; f < 8; f++) p = ffma2(qq[f].y, w0p[f], p);
            acc0 = add2(acc0, p & MASK);
            p = C1p;
#pragma unroll
            for (int f = 0; f < 8; f++) p = ffma2(qq[f].x, w1p[f], p);
            acc1 = add2(acc1, p & MASK);
            p = C1p;
#pragma unroll
            for (int f = 0; f < 8; f++) p = ffma2(qq[f].y, w1p[f], p);
            acc1 = add2(acc1, p & MASK);
        }
    } else {
        // warp 3: h1 in [224,256) is all zero-padding -> single-h loop
#pragma unroll 1
        for (int j4 = 0; j4 < 512; j4 += 4) {
            ulonglong2 qq[8];
#pragma unroll
            for (int f = 0; f < 8; f++)
                qq[f] = *(const ulonglong2*)(ftr + f * 512 + j4);
            u64t p;
            p = C0p;
#pragma unroll
            for (int f = 0; f < 8; f++) p = ffma2(qq[f].x, w0p[f], p);
            acc0 = add2(acc0, p & MASK);
            p = C0p;
#pragma unroll
            for (int f = 0; f < 8; f++) p = ffma2(qq[f].y, w0p[f], p);
            acc0 = add2(acc0, p & MASK);
        }
    }

    float S0 = C0, S1 = C1;
#pragma unroll
    for (int f = 0; f < 8; f++) { S0 += fm[f] * w0s[f]; S1 += fm[f] * w1s[f]; }
    float2 e0 = unpack2(acc0), e1 = unpack2(acc1);
    float hm0 = 0.505f * S0 + (0.495f / ND_) * (e0.x + e0.y);
    float hm1 = 0.505f * S1 + (0.495f / ND_) * (e1.x + e1.y);
    float* hmp = g_hm + (b * NT_ + i) * NH_;
    hmp[h0] = hm0;
    if (h1i < NH_) hmp[h1i] = hm1;
}

// ---------------------------------------------------------------------------
// Tail v6: 512 CTAs x 4 rows, 256 threads. W1/W2 staged cooperatively into
// double-buffered smem (contiguous float4 block copies, predicated ragged
// end), prefetch issued before compute, one __syncthreads per k-block.
// ---------------------------------------------------------------------------
#define W1F4 ((NH_ * NH_) / 4)   // 9604
#define W2F4 ((NH_ * KL_) / 4)   // 6272

__device__ __forceinline__ float4 ld4z(const float4* __restrict__ p, int idx, int lim) {
    return (idx < lim) ? __ldg(p + idx) : make_float4(0.f, 0.f, 0.f, 0.f);
}

__global__ __launch_bounds__(256) void tail_kernel(
    const float* __restrict__ W1, const float* __restrict__ b1,
    const float* __restrict__ W2, const float* __restrict__ b2,
    float* __restrict__ out)
{
    __shared__ __align__(16) float hm_s[RT_ * 208];
    __shared__ __align__(16) float h2_s[RT_ * 208];
    __shared__ __align__(16) float ws[2][16 * NH_];   // 2 x 12544 B

    int t = threadIdx.x;
    int row0 = blockIdx.x * RT_;
    bool act = (t < NH_);

    // zero pads of hm_s/h2_s
    for (int idx = t; idx < (RT_ * 208) / 4; idx += 256) {
        ((float4*)hm_s)[idx] = make_float4(0.f, 0.f, 0.f, 0.f);
        ((float4*)h2_s)[idx] = make_float4(0.f, 0.f, 0.f, 0.f);
    }
    __syncthreads();

    // stage hm rows + W1 block 0
    {
        const float4* src = (const float4*)g_hm;
        for (int idx = t; idx < RT_ * 49; idx += 256) {
            int r = idx / 49, c = idx - r * 49;
            ((float4*)hm_s)[r * 52 + c] = src[(row0 + r) * 49 + c];
        }
        const float4* w1v = (const float4*)W1;
        float4* dst = (float4*)ws[0];
        dst[t]       = __ldg(w1v + t);
        dst[t + 256] = __ldg(w1v + t + 256);
        dst[t + 512] = __ldg(w1v + t + 512);
        if (t < 16) dst[t + 768] = __ldg(w1v + t + 768);
    }
    __syncthreads();

    // ---- layer 1: thread t (<196) owns column h = t, 4-row ILP ----
    float bv1 = act ? b1[t] : 0.f;
    float a0 = bv1, a1 = bv1, a2 = bv1, a3 = bv1;
    {
        const float4* w1v = (const float4*)W1;
#pragma unroll 1
        for (int blk = 0; blk < 13; blk++) {
            int cur = blk & 1, nxt = cur ^ 1;
            bool pre = (blk < 12);
            float4 pf0, pf1, pf2, pf3;
            if (pre) {
                int goff = (blk + 1) * 784;
                pf0 = ld4z(w1v, goff + t,       W1F4);
                pf1 = ld4z(w1v, goff + t + 256, W1F4);
                pf2 = ld4z(w1v, goff + t + 512, W1F4);
                pf3 = (t < 16) ? ld4z(w1v, goff + t + 768, W1F4)
                               : make_float4(0.f, 0.f, 0.f, 0.f);
            }
            if (act) {
                const float* wb = ws[cur];
                int k0 = blk * 16;
#pragma unroll
                for (int q = 0; q < 4; q++) {
                    int kk = k0 + q * 4;
                    float4 h0 = *(const float4*)(hm_s + 0 * 208 + kk);
                    float4 h1 = *(const float4*)(hm_s + 1 * 208 + kk);
                    float4 h2 = *(const float4*)(hm_s + 2 * 208 + kk);
                    float4 h3 = *(const float4*)(hm_s + 3 * 208 + kk);
                    float w0v = wb[(q * 4 + 0) * NH_ + t];
                    float w1w = wb[(q * 4 + 1) * NH_ + t];
                    float w2w = wb[(q * 4 + 2) * NH_ + t];
                    float w3w = wb[(q * 4 + 3) * NH_ + t];
                    a0 = fmaf(h0.x, w0v, a0); a0 = fmaf(h0.y, w1w, a0);
                    a0 = fmaf(h0.z, w2w, a0); a0 = fmaf(h0.w, w3w, a0);
                    a1 = fmaf(h1.x, w0v, a1); a1 = fmaf(h1.y, w1w, a1);
                    a1 = fmaf(h1.z, w2w, a1); a1 = fmaf(h1.w, w3w, a1);
                    a2 = fmaf(h2.x, w0v, a2); a2 = fmaf(h2.y, w1w, a2);
                    a2 = fmaf(h2.z, w2w, a2); a2 = fmaf(h2.w, w3w, a2);
                    a3 = fmaf(h3.x, w0v, a3); a3 = fmaf(h3.y, w1w, a3);
                    a3 = fmaf(h3.z, w2w, a3); a3 = fmaf(h3.w, w3w, a3);
                }
            }
            if (pre) {
                float4* dst = (float4*)ws[nxt];
                dst[t] = pf0; dst[t + 256] = pf1; dst[t + 512] = pf2;
                if (t < 16) dst[t + 768] = pf3;
            }
            __syncthreads();
        }
    }
    if (act) {
        h2_s[0 * 208 + t] = fmaxf(a0, 0.01f * a0);
        h2_s[1 * 208 + t] = fmaxf(a1, 0.01f * a1);
        h2_s[2 * 208 + t] = fmaxf(a2, 0.01f * a2);
        h2_s[3 * 208 + t] = fmaxf(a3, 0.01f * a3);
    }
    // stage W2 block 0 (buffers free after the loop's final sync)
    {
        const float4* w2v = (const float4*)W2;
        float4* dst = (float4*)ws[0];
        dst[t]       = __ldg(w2v + t);
        dst[t + 256] = __ldg(w2v + t + 256);
    }
    __syncthreads();

    // ---- layer 2: o = t&127, row pair r0 = (t>>7)*2 ----
    {
        int o  = t & (KL_ - 1);
        int r0 = (t >> 7) * 2;
        float b0v = b2[o];
        float c0 = b0v, c1 = b0v;
        const float4* w2v = (const float4*)W2;
#pragma unroll 1
        for (int blk = 0; blk < 13; blk++) {
            int cur = blk & 1, nxt = cur ^ 1;
            bool pre = (blk < 12);
            float4 pf0, pf1;
            if (pre) {
                int goff = (blk + 1) * 512;
                pf0 = ld4z(w2v, goff + t,       W2F4);
                pf1 = ld4z(w2v, goff + t + 256, W2F4);
            }
            {
                const float* wb = ws[cur];
                int k0 = blk * 16;
#pragma unroll
                for (int q = 0; q < 4; q++) {
                    int kk = k0 + q * 4;
                    float4 h0 = *(const float4*)(h2_s + (r0 + 0) * 208 + kk);
                    float4 h1 = *(const float4*)(h2_s + (r0 + 1) * 208 + kk);
                    float w0v = wb[(q * 4 + 0) * KL_ + o];
                    float w1w = wb[(q * 4 + 1) * KL_ + o];
                    float w2w = wb[(q * 4 + 2) * KL_ + o];
                    float w3w = wb[(q * 4 + 3) * KL_ + o];
                    c0 = fmaf(h0.x, w0v, c0); c0 = fmaf(h0.y, w1w, c0);
                    c0 = fmaf(h0.z, w2w, c0); c0 = fmaf(h0.w, w3w, c0);
                    c1 = fmaf(h1.x, w0v, c1); c1 = fmaf(h1.y, w1w, c1);
                    c1 = fmaf(h1.z, w2w, c1); c1 = fmaf(h1.w, w3w, c1);
                }
            }
            if (pre) {
                float4* dst = (float4*)ws[nxt];
                dst[t] = pf0; dst[t + 256] = pf1;
            }
            __syncthreads();
        }
        out[(row0 + r0 + 0) * KL_ + o] = c0;
        out[(row0 + r0 + 1) * KL_ + o] = c1;
    }
}

// ---------------------------------------------------------------------------
extern "C" void kernel_launch(void* const* d_in, const int* in_sizes, int n_in,
                              void* d_out, int out_size) {
    const float* x0    = (const float*)d_in[0];
    const float* x     = (const float*)d_in[1];
    const float* N     = (const float*)d_in[2];
    const float* basis = (const float*)d_in[3];
    const float* v     = (const float*)d_in[4];
    const float* W0    = (const float*)d_in[5];
    const float* b0    = (const float*)d_in[6];
    const float* W1    = (const float*)d_in[7];
    const float* b1    = (const float*)d_in[8];
    const float* W2    = (const float*)d_in[9];
    const float* b2    = (const float*)d_in[10];

    precomp_kernel<<<B_, HP_>>>(W0, b0, basis);
    main_kernel<<<B_ * NT_, 128>>>(x0, x, N, v);
    tail_kernel<<<(B_ * NT_) / RT_, 256>>>(W1, b1, W2, b2, (float*)d_out);
}

// round 12
// speedup vs baseline: 1.0876x; 1.0699x over previous
#include <cuda_runtime.h>

#define B_   2
#define NT_  1024
#define ND_  512
#define NH_  196
#define HP_  256      // padded hidden dim (zeros for h >= 196)
#define KL_  128
#define ROWS_ 16

// scratch (device globals: allocation-free)
__device__ float g_wj[B_ * 8 * HP_];    // per-j weights
__device__ float g_wc[B_ * 10 * HP_];   // per-i weights
__device__ float g_hm[B_ * NT_ * NH_];  // pooled hidden, pre-W1

typedef unsigned long long u64t;

__device__ __forceinline__ u64t pack2(float x, float y) {
    u64t r; asm("mov.b64 %0, {%1, %2};" : "=l"(r) : "f"(x), "f"(y)); return r;
}
__device__ __forceinline__ float2 unpack2(u64t v) {
    float2 r; asm("mov.b64 {%0, %1}, %2;" : "=f"(r.x), "=f"(r.y) : "l"(v)); return r;
}
__device__ __forceinline__ u64t ffma2(u64t a, u64t b, u64t c) {
    u64t d; asm("fma.rn.f32x2 %0, %1, %2, %3;" : "=l"(d) : "l"(a), "l"(b), "l"(c)); return d;
}
__device__ __forceinline__ u64t add2(u64t a, u64t b) {
    u64t d; asm("add.rn.f32x2 %0, %1, %2;" : "=l"(d) : "l"(a), "l"(b)); return d;
}

// ---------------------------------------------------------------------------
// Kernel 1: fold basis into W0 rows (tiny)  [R9 verbatim]
// ---------------------------------------------------------------------------
__global__ void precomp_kernel(const float* __restrict__ W0,
                               const float* __restrict__ b0,
                               const float* __restrict__ basis) {
    int b = blockIdx.x, h = threadIdx.x;
    float* wj = g_wj + b * 8 * HP_;
    float* wc = g_wc + b * 10 * HP_;
    if (h >= NH_) {
        for (int r = 0; r < 8;  r++) wj[r * HP_ + h] = 0.f;
        for (int r = 0; r < 10; r++) wc[r * HP_ + h] = 0.f;
        return;
    }
    const float* bs = basis + b * 6 * 3;
    wj[0 * HP_ + h] = W0[15 * NH_ + h];
    wj[4 * HP_ + h] = W0[22 * NH_ + h];
    wc[0 * HP_ + h] = W0[0 * NH_ + h];
    wc[1 * HP_ + h] = W0[1 * NH_ + h];
    wc[5 * HP_ + h] = W0[8 * NH_ + h];
    wc[9 * HP_ + h] = b0[h];
    for (int d = 0; d < 3; d++) {
        float m0x = 0.f, m0v = 0.f, m1 = 0.f, m2 = 0.f;
        for (int k = 0; k < 6; k++) {
            float bb = bs[k * 3 + d];
            m0x += bb * W0[(2  + k) * NH_ + h];
            m0v += bb * W0[(9  + k) * NH_ + h];
            m1  += bb * W0[(16 + k) * NH_ + h];
            m2  += bb * W0[(23 + k) * NH_ + h];
        }
        wj[(1 + d) * HP_ + h] = m1;
        wj[(5 + d) * HP_ + h] = m2;
        wc[(2 + d) * HP_ + h] = m0x;
        wc[(6 + d) * HP_ + h] = m0v;
    }
}

// ---------------------------------------------------------------------------
// Kernel 2 (R1/R5/R7/R9-proven, untouched): one CTA per (b,i), 128 threads.
// ---------------------------------------------------------------------------
__global__ __launch_bounds__(128) void main_kernel(
    const float* __restrict__ x0g, const float* __restrict__ xg,
    const float* __restrict__ Ng,  const float* __restrict__ vg) {
    __shared__ float4 ftr4[8 * 128];           // features transposed: ftr[f][512]
    float* ftr = (float*)ftr4;
    __shared__ float red[32];

    int t = threadIdx.x;
    int blk = blockIdx.x;
    int b = blk >> 10, i = blk & (NT_ - 1);
    int lane = t & 31, w = t >> 5;
    int base = (b * NT_ + i) * ND_ * 3;

    // --- phase 1: vbulk (keep v in regs for phase 2) ---
    float vxr[4], vyr[4], vzr[4];
    float s0 = 0.f, s1 = 0.f, s2 = 0.f;
#pragma unroll
    for (int r = 0; r < 4; r++) {
        int j = t + r * 128;
        const float* vp = vg + base + j * 3;
        float a = vp[0], bb = vp[1], c = vp[2];
        vxr[r] = a; vyr[r] = bb; vzr[r] = c;
        s0 += a; s1 += bb; s2 += c;
    }
#pragma unroll
    for (int off = 16; off; off >>= 1) {
        s0 += __shfl_xor_sync(0xffffffffu, s0, off);
        s1 += __shfl_xor_sync(0xffffffffu, s1, off);
        s2 += __shfl_xor_sync(0xffffffffu, s2, off);
    }
    if (lane == 0) { red[w * 8 + 0] = s0; red[w * 8 + 1] = s1; red[w * 8 + 2] = s2; }
    __syncthreads();
    float vb0 = (red[0] + red[8]  + red[16] + red[24]) * (1.f / ND_);
    float vb1 = (red[1] + red[9]  + red[17] + red[25]) * (1.f / ND_);
    float vb2 = (red[2] + red[10] + red[18] + red[26]) * (1.f / ND_);
    __syncthreads();

    // --- phase 2: stage per-j features + per-feature sums ---
    float fs[8] = {0.f, 0.f, 0.f, 0.f, 0.f, 0.f, 0.f, 0.f};
#pragma unroll
    for (int r = 0; r < 4; r++) {
        int j = t + r * 128;
        const float* xp = xg + base + j * 3;
        float a = xp[0], bb = xp[1], c = xp[2];
        float d  = a * a + bb * bb + c * c;
        float ri = rsqrtf(d);
        float n  = d * ri;
        float e1 = a * ri, e2 = bb * ri, e3 = c * ri;
        ftr[0 * 512 + j] = n;  ftr[1 * 512 + j] = e1;
        ftr[2 * 512 + j] = e2; ftr[3 * 512 + j] = e3;
        fs[0] += n; fs[1] += e1; fs[2] += e2; fs[3] += e3;
        float c0 = vxr[r] - vb0, c1 = vyr[r] - vb1, c2 = vzr[r] - vb2;
        d  = c0 * c0 + c1 * c1 + c2 * c2;
        ri = rsqrtf(d);
        n  = d * ri;
        e1 = c0 * ri; e2 = c1 * ri; e3 = c2 * ri;
        ftr[4 * 512 + j] = n;  ftr[5 * 512 + j] = e1;
        ftr[6 * 512 + j] = e2; ftr[7 * 512 + j] = e3;
        fs[4] += n; fs[5] += e1; fs[6] += e2; fs[7] += e3;
    }
#pragma unroll
    for (int off = 16; off; off >>= 1)
#pragma unroll
        for (int f = 0; f < 8; f++) fs[f] += __shfl_xor_sync(0xffffffffu, fs[f], off);
    if (lane == 0) {
#pragma unroll
        for (int f = 0; f < 8; f++) red[w * 8 + f] = fs[f];
    }
    __syncthreads();
    float fm[8];
#pragma unroll
    for (int f = 0; f < 8; f++)
        fm[f] = (red[f] + red[8 + f] + red[16 + f] + red[24 + f]) * (1.f / ND_);

    // --- per-i constant C (cheap, redundant per thread) ---
    float Nv = Ng[b * NT_ + i];
    const float* x0p = x0g + (b * NT_ + i) * 3;
    float p0 = x0p[0], p1 = x0p[1], p2 = x0p[2];
    float d0 = p0 * p0 + p1 * p1 + p2 * p2;
    float ri0 = rsqrtf(d0);
    float x0n = d0 * ri0;
    float u0 = p0 * ri0, u1 = p1 * ri0, u2 = p2 * ri0;
    float dv = vb0 * vb0 + vb1 * vb1 + vb2 * vb2;
    float riv = rsqrtf(dv);
    float vbn = dv * riv;
    float q0 = vb0 * riv, q1 = vb1 * riv, q2 = vb2 * riv;

    const float* wj = g_wj + b * 8 * HP_;
    const float* wc = g_wc + b * 10 * HP_;
    int h0 = t, h1i = t + 128;

    float C0, C1;
    {
        float c;
        c  = wc[9 * HP_ + h0];
        c += Nv  * wc[0 * HP_ + h0];
        c += x0n * wc[1 * HP_ + h0];
        c += u0 * wc[2 * HP_ + h0] + u1 * wc[3 * HP_ + h0] + u2 * wc[4 * HP_ + h0];
        c += vbn * wc[5 * HP_ + h0];
        c += q0 * wc[6 * HP_ + h0] + q1 * wc[7 * HP_ + h0] + q2 * wc[8 * HP_ + h0];
        C0 = c;
        c  = wc[9 * HP_ + h1i];
        c += Nv  * wc[0 * HP_ + h1i];
        c += x0n * wc[1 * HP_ + h1i];
        c += u0 * wc[2 * HP_ + h1i] + u1 * wc[3 * HP_ + h1i] + u2 * wc[4 * HP_ + h1i];
        c += vbn * wc[5 * HP_ + h1i];
        c += q0 * wc[6 * HP_ + h1i] + q1 * wc[7 * HP_ + h1i] + q2 * wc[8 * HP_ + h1i];
        C1 = c;
    }

    float w0s[8], w1s[8];
    u64t  w0p[8], w1p[8];
#pragma unroll
    for (int f = 0; f < 8; f++) {
        w0s[f] = wj[f * HP_ + h0];
        w1s[f] = wj[f * HP_ + h1i];
        w0p[f] = pack2(w0s[f], w0s[f]);
        w1p[f] = pack2(w1s[f], w1s[f]);
    }
    u64t C0p = pack2(C0, C0), C1p = pack2(C1, C1);

    // --- phase 3: hot loop. acc = sum_j |pre_j| for 2 h's, f32x2 over j ---
    const u64t MASK = 0x7FFFFFFF7FFFFFFFULL;
    u64t acc0 = 0ull, acc1 = 0ull;
#pragma unroll 1
    for (int j4 = 0; j4 < 512; j4 += 4) {
        ulonglong2 qq[8];
#pragma unroll
        for (int f = 0; f < 8; f++)
            qq[f] = *(const ulonglong2*)(ftr + f * 512 + j4);
        u64t p;
        p = C0p;
#pragma unroll
        for (int f = 0; f < 8; f++) p = ffma2(qq[f].x, w0p[f], p);
        acc0 = add2(acc0, p & MASK);
        p = C0p;
#pragma unroll
        for (int f = 0; f < 8; f++) p = ffma2(qq[f].y, w0p[f], p);
        acc0 = add2(acc0, p & MASK);
        p = C1p;
#pragma unroll
        for (int f = 0; f < 8; f++) p = ffma2(qq[f].x, w1p[f], p);
        acc1 = add2(acc1, p & MASK);
        p = C1p;
#pragma unroll
        for (int f = 0; f < 8; f++) p = ffma2(qq[f].y, w1p[f], p);
        acc1 = add2(acc1, p & MASK);
    }

    // mean(leaky) = 0.505*mean(pre) + 0.495*mean|pre|; mean(pre) is analytic
    float S0 = C0, S1 = C1;
#pragma unroll
    for (int f = 0; f < 8; f++) { S0 += fm[f] * w0s[f]; S1 += fm[f] * w1s[f]; }
    float2 e0 = unpack2(acc0), e1 = unpack2(acc1);
    float hm0 = 0.505f * S0 + (0.495f / ND_) * (e0.x + e0.y);
    float hm1 = 0.505f * S1 + (0.495f / ND_) * (e1.x + e1.y);
    float* hmp = g_hm + (b * NT_ + i) * NH_;
    hmp[h0] = hm0;
    if (h1i < NH_) hmp[h1i] = hm1;
}

// ---------------------------------------------------------------------------
// Tail (R4-measured-best, 31.2us): 128 CTAs x 16 rows, 256 threads.
// Whole W1 staged in dynamic smem; hm transposed+duplicated (h,h) for f32x2
// col-pair register tiling; lane mapping puts same-column tiles in adjacent
// lanes. Layer 2 reuses the weight buffer (W2).
// ---------------------------------------------------------------------------
#define HMTD_N (NH_ * 17)                // u64 elems, padded stride 17
#define TAIL_SMEM_BYTES (2 * HMTD_N * 8 + NH_ * NH_ * 4)

__global__ __launch_bounds__(256) void tail_kernel(
    const float* __restrict__ W1, const float* __restrict__ b1,
    const float* __restrict__ W2, const float* __restrict__ b2,
    float* __restrict__ out)
{
    extern __shared__ __align__(16) char sm_raw[];
    u64t*  hmTd = (u64t*)sm_raw;             // [k][r] pad 17, (h,h) dup
    u64t*  h2Td = hmTd + HMTD_N;             // [k][r] pad 17, (h,h) dup
    float* wt   = (float*)(h2Td + HMTD_N);   // W1 (196x196) then W2 (196x128)

    int t = threadIdx.x;
    int row0 = blockIdx.x * ROWS_;

    // stage hm (coalesced read, padded dup store)
    for (int idx = t; idx < ROWS_ * NH_; idx += 256) {
        int r = idx / NH_;
        int k = idx - r * NH_;
        float v = g_hm[(row0 + r) * NH_ + k];
        hmTd[k * 17 + r] = pack2(v, v);
    }
    // stage full W1 (float4)
    {
        const float4* W14 = (const float4*)W1;
        float4* wt4 = (float4*)wt;
        for (int idx = t; idx < (NH_ * NH_) / 4; idx += 256)
            wt4[idx] = W14[idx];
    }
    __syncthreads();

    // ---- layer 1: 196 threads; rt = t&3 (adjacent lanes share columns) ----
    if (t < 196) {
        int rt = t & 3, ct = t >> 2;         // ct in 0..48
        int r0 = rt * 4, c0 = ct * 4;
        u64t a00 = 0, a01 = 0, a10 = 0, a11 = 0;
        u64t a20 = 0, a21 = 0, a30 = 0, a31 = 0;
#pragma unroll 4
        for (int k = 0; k < NH_; k++) {
            u64t w01 = *(const u64t*)(wt + k * NH_ + c0);
            u64t w23 = *(const u64t*)(wt + k * NH_ + c0 + 2);
            u64t h0 = hmTd[k * 17 + r0];
            u64t h1 = hmTd[k * 17 + r0 + 1];
            u64t h2 = hmTd[k * 17 + r0 + 2];
            u64t h3 = hmTd[k * 17 + r0 + 3];
            a00 = ffma2(h0, w01, a00);  a01 = ffma2(h0, w23, a01);
            a10 = ffma2(h1, w01, a10);  a11 = ffma2(h1, w23, a11);
            a20 = ffma2(h2, w01, a20);  a21 = ffma2(h2, w23, a21);
            a30 = ffma2(h3, w01, a30);  a31 = ffma2(h3, w23, a31);
        }
        float bA0 = b1[c0], bA1 = b1[c0 + 1], bB0 = b1[c0 + 2], bB1 = b1[c0 + 3];
        u64t accs[8] = {a00, a01, a10, a11, a20, a21, a30, a31};
#pragma unroll
        for (int rr = 0; rr < 4; rr++) {
            float2 eA = unpack2(accs[rr * 2]);
            float2 eB = unpack2(accs[rr * 2 + 1]);
            float z0 = eA.x + bA0, z1 = eA.y + bA1;
            float z2 = eB.x + bB0, z3 = eB.y + bB1;
            z0 = fmaxf(z0, 0.01f * z0); z1 = fmaxf(z1, 0.01f * z1);
            z2 = fmaxf(z2, 0.01f * z2); z3 = fmaxf(z3, 0.01f * z3);
            h2Td[(c0 + 0) * 17 + r0 + rr] = pack2(z0, z0);
            h2Td[(c0 + 1) * 17 + r0 + rr] = pack2(z1, z1);
            h2Td[(c0 + 2) * 17 + r0 + rr] = pack2(z2, z2);
            h2Td[(c0 + 3) * 17 + r0 + rr] = pack2(z3, z3);
        }
    }
    __syncthreads();

    // stage W2 into wt (reuse)
    {
        const float4* W24 = (const float4*)W2;
        float4* wt4 = (float4*)wt;
        for (int idx = t; idx < (NH_ * KL_) / 4; idx += 256)
            wt4[idx] = W24[idx];
    }
    __syncthreads();

    // ---- layer 2: all 256 threads; rt = t&7 (adjacent lanes share columns) ----
    {
        int rt = t & 7, ct = t >> 3;         // ct in 0..31
        int r0 = rt * 2, c0 = ct * 4;
        u64t a00 = 0, a01 = 0, a10 = 0, a11 = 0;
#pragma unroll 4
        for (int k = 0; k < NH_; k++) {
            u64t w01 = *(const u64t*)(wt + k * KL_ + c0);
            u64t w23 = *(const u64t*)(wt + k * KL_ + c0 + 2);
            u64t h0 = h2Td[k * 17 + r0];
            u64t h1 = h2Td[k * 17 + r0 + 1];
            a00 = ffma2(h0, w01, a00);  a01 = ffma2(h0, w23, a01);
            a10 = ffma2(h1, w01, a10);  a11 = ffma2(h1, w23, a11);
        }
        float bA0 = b2[c0], bA1 = b2[c0 + 1], bB0 = b2[c0 + 2], bB1 = b2[c0 + 3];
        float2 e;
        e = unpack2(a00);
        out[(row0 + r0) * KL_ + c0]     = e.x + bA0;
        out[(row0 + r0) * KL_ + c0 + 1] = e.y + bA1;
        e = unpack2(a01);
        out[(row0 + r0) * KL_ + c0 + 2] = e.x + bB0;
        out[(row0 + r0) * KL_ + c0 + 3] = e.y + bB1;
        e = unpack2(a10);
        out[(row0 + r0 + 1) * KL_ + c0]     = e.x + bA0;
        out[(row0 + r0 + 1) * KL_ + c0 + 1] = e.y + bA1;
        e = unpack2(a11);
        out[(row0 + r0 + 1) * KL_ + c0 + 2] = e.x + bB0;
        out[(row0 + r0 + 1) * KL_ + c0 + 3] = e.y + bB1;
    }
}

// ---------------------------------------------------------------------------
extern "C" void kernel_launch(void* const* d_in, const int* in_sizes, int n_in,
                              void* d_out, int out_size) {
    const float* x0    = (const float*)d_in[0];
    const float* x     = (const float*)d_in[1];
    const float* N     = (const float*)d_in[2];
    const float* basis = (const float*)d_in[3];
    const float* v     = (const float*)d_in[4];
    const float* W0    = (const float*)d_in[5];
    const float* b0    = (const float*)d_in[6];
    const float* W1    = (const float*)d_in[7];
    const float* b1    = (const float*)d_in[8];
    const float* W2    = (const float*)d_in[9];
    const float* b2    = (const float*)d_in[10];

    cudaFuncSetAttribute(tail_kernel,
                         cudaFuncAttributeMaxDynamicSharedMemorySize,
                         TAIL_SMEM_BYTES);

    precomp_kernel<<<B_, HP_>>>(W0, b0, basis);
    main_kernel<<<B_ * NT_, 128>>>(x0, x, N, v);
    tail_kernel<<<(B_ * NT_) / ROWS_, 256, TAIL_SMEM_BYTES>>>(
        W1, b1, W2, b2, (float*)d_out);
}

// round 13
// speedup vs baseline: 1.1452x; 1.0529x over previous
#include <cuda_runtime.h>

#define B_   2
#define NT_  1024
#define ND_  512
#define NH_  196
#define HP_  256      // padded hidden dim (zeros for h >= 196)
#define KL_  128
#define ROWS2_ 4

// scratch (device globals: allocation-free)
__device__ float g_wj[B_ * 8 * HP_];
__device__ float g_wc[B_ * 10 * HP_];
__device__ float g_hm[B_ * NT_ * NH_];

typedef unsigned long long u64t;

__device__ __forceinline__ u64t pack2(float x, float y) {
    u64t r; asm("mov.b64 %0, {%1, %2};" : "=l"(r) : "f"(x), "f"(y)); return r;
}
__device__ __forceinline__ float2 unpack2(u64t v) {
    float2 r; asm("mov.b64 {%0, %1}, %2;" : "=f"(r.x), "=f"(r.y) : "l"(v)); return r;
}
__device__ __forceinline__ u64t ffma2(u64t a, u64t b, u64t c) {
    u64t d; asm("fma.rn.f32x2 %0, %1, %2, %3;" : "=l"(d) : "l"(a), "l"(b), "l"(c)); return d;
}
__device__ __forceinline__ u64t add2(u64t a, u64t b) {
    u64t d; asm("add.rn.f32x2 %0, %1, %2;" : "=l"(d) : "l"(a), "l"(b)); return d;
}

// ---------------------------------------------------------------------------
// Kernel 1: fold basis into W0 rows (tiny)  [R9 verbatim]
// ---------------------------------------------------------------------------
__global__ void precomp_kernel(const float* __restrict__ W0,
                               const float* __restrict__ b0,
                               const float* __restrict__ basis) {
    int b = blockIdx.x, h = threadIdx.x;
    float* wj = g_wj + b * 8 * HP_;
    float* wc = g_wc + b * 10 * HP_;
    if (h >= NH_) {
        for (int r = 0; r < 8;  r++) wj[r * HP_ + h] = 0.f;
        for (int r = 0; r < 10; r++) wc[r * HP_ + h] = 0.f;
        return;
    }
    const float* bs = basis + b * 6 * 3;
    wj[0 * HP_ + h] = W0[15 * NH_ + h];
    wj[4 * HP_ + h] = W0[22 * NH_ + h];
    wc[0 * HP_ + h] = W0[0 * NH_ + h];
    wc[1 * HP_ + h] = W0[1 * NH_ + h];
    wc[5 * HP_ + h] = W0[8 * NH_ + h];
    wc[9 * HP_ + h] = b0[h];
    for (int d = 0; d < 3; d++) {
        float m0x = 0.f, m0v = 0.f, m1 = 0.f, m2 = 0.f;
        for (int k = 0; k < 6; k++) {
            float bb = bs[k * 3 + d];
            m0x += bb * W0[(2  + k) * NH_ + h];
            m0v += bb * W0[(9  + k) * NH_ + h];
            m1  += bb * W0[(16 + k) * NH_ + h];
            m2  += bb * W0[(23 + k) * NH_ + h];
        }
        wj[(1 + d) * HP_ + h] = m1;
        wj[(5 + d) * HP_ + h] = m2;
        wc[(2 + d) * HP_ + h] = m0x;
        wc[(6 + d) * HP_ + h] = m0v;
    }
}

// ---------------------------------------------------------------------------
// Kernel 2: R9 main with ONE change — phase-3 warp specialization.
// Warps 0-2: 2-h loop (unchanged). Warp 3: 1-h loop (its h1 range [224,256)
// is all zero-padding). Everything else byte-identical to R9.
// ---------------------------------------------------------------------------
__global__ __launch_bounds__(128) void main_kernel(
    const float* __restrict__ x0g, const float* __restrict__ xg,
    const float* __restrict__ Ng,  const float* __restrict__ vg) {
    __shared__ float4 ftr4[8 * 128];
    float* ftr = (float*)ftr4;
    __shared__ float red[32];

    int t = threadIdx.x;
    int blk = blockIdx.x;
    int b = blk >> 10, i = blk & (NT_ - 1);
    int lane = t & 31, w = t >> 5;
    int base = (b * NT_ + i) * ND_ * 3;

    // --- phase 1: vbulk ---
    float vxr[4], vyr[4], vzr[4];
    float s0 = 0.f, s1 = 0.f, s2 = 0.f;
#pragma unroll
    for (int r = 0; r < 4; r++) {
        int j = t + r * 128;
        const float* vp = vg + base + j * 3;
        float a = vp[0], bb = vp[1], c = vp[2];
        vxr[r] = a; vyr[r] = bb; vzr[r] = c;
        s0 += a; s1 += bb; s2 += c;
    }
#pragma unroll
    for (int off = 16; off; off >>= 1) {
        s0 += __shfl_xor_sync(0xffffffffu, s0, off);
        s1 += __shfl_xor_sync(0xffffffffu, s1, off);
        s2 += __shfl_xor_sync(0xffffffffu, s2, off);
    }
    if (lane == 0) { red[w * 8 + 0] = s0; red[w * 8 + 1] = s1; red[w * 8 + 2] = s2; }
    __syncthreads();
    float vb0 = (red[0] + red[8]  + red[16] + red[24]) * (1.f / ND_);
    float vb1 = (red[1] + red[9]  + red[17] + red[25]) * (1.f / ND_);
    float vb2 = (red[2] + red[10] + red[18] + red[26]) * (1.f / ND_);
    __syncthreads();

    // --- phase 2: features + per-feature sums ---
    float fs[8] = {0.f, 0.f, 0.f, 0.f, 0.f, 0.f, 0.f, 0.f};
#pragma unroll
    for (int r = 0; r < 4; r++) {
        int j = t + r * 128;
        const float* xp = xg + base + j * 3;
        float a = xp[0], bb = xp[1], c = xp[2];
        float d  = a * a + bb * bb + c * c;
        float ri = rsqrtf(d);
        float n  = d * ri;
        float e1 = a * ri, e2 = bb * ri, e3 = c * ri;
        ftr[0 * 512 + j] = n;  ftr[1 * 512 + j] = e1;
        ftr[2 * 512 + j] = e2; ftr[3 * 512 + j] = e3;
        fs[0] += n; fs[1] += e1; fs[2] += e2; fs[3] += e3;
        float c0 = vxr[r] - vb0, c1 = vyr[r] - vb1, c2 = vzr[r] - vb2;
        d  = c0 * c0 + c1 * c1 + c2 * c2;
        ri = rsqrtf(d);
        n  = d * ri;
        e1 = c0 * ri; e2 = c1 * ri; e3 = c2 * ri;
        ftr[4 * 512 + j] = n;  ftr[5 * 512 + j] = e1;
        ftr[6 * 512 + j] = e2; ftr[7 * 512 + j] = e3;
        fs[4] += n; fs[5] += e1; fs[6] += e2; fs[7] += e3;
    }
#pragma unroll
    for (int off = 16; off; off >>= 1)
#pragma unroll
        for (int f = 0; f < 8; f++) fs[f] += __shfl_xor_sync(0xffffffffu, fs[f], off);
    if (lane == 0) {
#pragma unroll
        for (int f = 0; f < 8; f++) red[w * 8 + f] = fs[f];
    }
    __syncthreads();
    float fm[8];
#pragma unroll
    for (int f = 0; f < 8; f++)
        fm[f] = (red[f] + red[8 + f] + red[16 + f] + red[24 + f]) * (1.f / ND_);

    // --- per-i constant C ---
    float Nv = Ng[b * NT_ + i];
    const float* x0p = x0g + (b * NT_ + i) * 3;
    float p0 = x0p[0], p1 = x0p[1], p2 = x0p[2];
    float d0 = p0 * p0 + p1 * p1 + p2 * p2;
    float ri0 = rsqrtf(d0);
    float x0n = d0 * ri0;
    float u0 = p0 * ri0, u1 = p1 * ri0, u2 = p2 * ri0;
    float dv = vb0 * vb0 + vb1 * vb1 + vb2 * vb2;
    float riv = rsqrtf(dv);
    float vbn = dv * riv;
    float q0 = vb0 * riv, q1 = vb1 * riv, q2 = vb2 * riv;

    const float* wj = g_wj + b * 8 * HP_;
    const float* wc = g_wc + b * 10 * HP_;
    int h0 = t, h1i = t + 128;

    float C0, C1;
    {
        float c;
        c  = wc[9 * HP_ + h0];
        c += Nv  * wc[0 * HP_ + h0];
        c += x0n * wc[1 * HP_ + h0];
        c += u0 * wc[2 * HP_ + h0] + u1 * wc[3 * HP_ + h0] + u2 * wc[4 * HP_ + h0];
        c += vbn * wc[5 * HP_ + h0];
        c += q0 * wc[6 * HP_ + h0] + q1 * wc[7 * HP_ + h0] + q2 * wc[8 * HP_ + h0];
        C0 = c;
        c  = wc[9 * HP_ + h1i];
        c += Nv  * wc[0 * HP_ + h1i];
        c += x0n * wc[1 * HP_ + h1i];
        c += u0 * wc[2 * HP_ + h1i] + u1 * wc[3 * HP_ + h1i] + u2 * wc[4 * HP_ + h1i];
        c += vbn * wc[5 * HP_ + h1i];
        c += q0 * wc[6 * HP_ + h1i] + q1 * wc[7 * HP_ + h1i] + q2 * wc[8 * HP_ + h1i];
        C1 = c;
    }

    float w0s[8], w1s[8];
    u64t  w0p[8], w1p[8];
#pragma unroll
    for (int f = 0; f < 8; f++) {
        w0s[f] = wj[f * HP_ + h0];
        w1s[f] = wj[f * HP_ + h1i];
        w0p[f] = pack2(w0s[f], w0s[f]);
        w1p[f] = pack2(w1s[f], w1s[f]);
    }
    u64t C0p = pack2(C0, C0), C1p = pack2(C1, C1);

    // --- phase 3: hot loop (warp-specialized; ONLY change vs R9) ---
    const u64t MASK = 0x7FFFFFFF7FFFFFFFULL;
    u64t acc0 = 0ull, acc1 = 0ull;
    if (w < 3) {
#pragma unroll 1
        for (int j4 = 0; j4 < 512; j4 += 4) {
            ulonglong2 qq[8];
#pragma unroll
            for (int f = 0; f < 8; f++)
                qq[f] = *(const ulonglong2*)(ftr + f * 512 + j4);
            u64t p;
            p = C0p;
#pragma unroll
            for (int f = 0; f < 8; f++) p = ffma2(qq[f].x, w0p[f], p);
            acc0 = add2(acc0, p & MASK);
            p = C0p;
#pragma unroll
            for (int f = 0; f < 8; f++) p = ffma2(qq[f].y, w0p[f], p);
            acc0 = add2(acc0, p & MASK);
            p = C1p;
#pragma unroll
            for (int f = 0; f < 8; f++) p = ffma2(qq[f].x, w1p[f], p);
            acc1 = add2(acc1, p & MASK);
            p = C1p;
#pragma unroll
            for (int f = 0; f < 8; f++) p = ffma2(qq[f].y, w1p[f], p);
            acc1 = add2(acc1, p & MASK);
        }
    } else {
#pragma unroll 1
        for (int j4 = 0; j4 < 512; j4 += 4) {
            ulonglong2 qq[8];
#pragma unroll
            for (int f = 0; f < 8; f++)
                qq[f] = *(const ulonglong2*)(ftr + f * 512 + j4);
            u64t p;
            p = C0p;
#pragma unroll
            for (int f = 0; f < 8; f++) p = ffma2(qq[f].x, w0p[f], p);
            acc0 = add2(acc0, p & MASK);
            p = C0p;
#pragma unroll
            for (int f = 0; f < 8; f++) p = ffma2(qq[f].y, w0p[f], p);
            acc0 = add2(acc0, p & MASK);
        }
    }

    float S0 = C0, S1 = C1;
#pragma unroll
    for (int f = 0; f < 8; f++) { S0 += fm[f] * w0s[f]; S1 += fm[f] * w1s[f]; }
    float2 e0 = unpack2(acc0), e1 = unpack2(acc1);
    float hm0 = 0.505f * S0 + (0.495f / ND_) * (e0.x + e0.y);
    float hm1 = 0.505f * S1 + (0.495f / ND_) * (e1.x + e1.y);
    float* hmp = g_hm + (b * NT_ + i) * NH_;
    hmp[h0] = hm0;
    if (h1i < NH_) hmp[h1i] = hm1;
}

// ---------------------------------------------------------------------------
// Tail v5 (R9 verbatim): 512 CTAs x 4 rows, 256 threads, pipelined W prefetch.
// ---------------------------------------------------------------------------
#define KP_ 208

__global__ __launch_bounds__(256) void tail_kernel(
    const float* __restrict__ W1, const float* __restrict__ b1,
    const float* __restrict__ W2, const float* __restrict__ b2,
    float* __restrict__ out)
{
    __shared__ __align__(16) float hm_s[ROWS2_ * KP_];
    __shared__ __align__(16) float h2_s[ROWS2_ * KP_];

    int t = threadIdx.x;
    int row0 = blockIdx.x * ROWS2_;

    {
        float4* z0 = (float4*)hm_s;
        float4* z1 = (float4*)h2_s;
        for (int idx = t; idx < (ROWS2_ * KP_) / 4; idx += 256) {
            z0[idx] = make_float4(0.f, 0.f, 0.f, 0.f);
            z1[idx] = make_float4(0.f, 0.f, 0.f, 0.f);
        }
    }
    __syncthreads();
    {
        const float4* src = (const float4*)g_hm;
        float4* dst = (float4*)hm_s;
        for (int idx = t; idx < ROWS2_ * 49; idx += 256) {
            int r = idx / 49, c = idx - r * 49;
            dst[r * (KP_ / 4) + c] = src[(row0 + r) * 49 + c];
        }
    }
    __syncthreads();

    if (t < NH_) {
        float bv = b1[t];
        float a0 = bv, a1 = bv, a2 = bv, a3 = bv;
        float wc[16];
#pragma unroll
        for (int u = 0; u < 16; u++) wc[u] = W1[u * NH_ + t];
#pragma unroll 1
        for (int blk = 0; blk < 13; blk++) {
            int k  = blk * 16;
            int kn = k + 16;
            float wn[16];
#pragma unroll
            for (int u = 0; u < 16; u++)
                wn[u] = (kn + u < NH_) ? W1[(kn + u) * NH_ + t] : 0.f;
#pragma unroll
            for (int c4 = 0; c4 < 4; c4++) {
                int kk = k + c4 * 4;
                float4 h0 = *(const float4*)(hm_s + 0 * KP_ + kk);
                float4 h1 = *(const float4*)(hm_s + 1 * KP_ + kk);
                float4 h2 = *(const float4*)(hm_s + 2 * KP_ + kk);
                float4 h3 = *(const float4*)(hm_s + 3 * KP_ + kk);
                float w0 = wc[c4 * 4 + 0], w1 = wc[c4 * 4 + 1];
                float w2 = wc[c4 * 4 + 2], w3 = wc[c4 * 4 + 3];
                a0 = fmaf(h0.x, w0, a0); a0 = fmaf(h0.y, w1, a0);
                a0 = fmaf(h0.z, w2, a0); a0 = fmaf(h0.w, w3, a0);
                a1 = fmaf(h1.x, w0, a1); a1 = fmaf(h1.y, w1, a1);
                a1 = fmaf(h1.z, w2, a1); a1 = fmaf(h1.w, w3, a1);
                a2 = fmaf(h2.x, w0, a2); a2 = fmaf(h2.y, w1, a2);
                a2 = fmaf(h2.z, w2, a2); a2 = fmaf(h2.w, w3, a2);
                a3 = fmaf(h3.x, w0, a3); a3 = fmaf(h3.y, w1, a3);
                a3 = fmaf(h3.z, w2, a3); a3 = fmaf(h3.w, w3, a3);
            }
#pragma unroll
            for (int u = 0; u < 16; u++) wc[u] = wn[u];
        }
        h2_s[0 * KP_ + t] = fmaxf(a0, 0.01f * a0);
        h2_s[1 * KP_ + t] = fmaxf(a1, 0.01f * a1);
        h2_s[2 * KP_ + t] = fmaxf(a2, 0.01f * a2);
        h2_s[3 * KP_ + t] = fmaxf(a3, 0.01f * a3);
    }
    __syncthreads();

    {
        int o  = t & (KL_ - 1);
        int r0 = (t >> 7) * 2;
        float bv = b2[o];
        float a0 = bv, a1 = bv;
        float wc[16];
#pragma unroll
        for (int u = 0; u < 16; u++) wc[u] = W2[u * KL_ + o];
#pragma unroll 1
        for (int blk = 0; blk < 13; blk++) {
            int k  = blk * 16;
            int kn = k + 16;
            float wn[16];
#pragma unroll
            for (int u = 0; u < 16; u++)
                wn[u] = (kn + u < NH_) ? W2[(kn + u) * KL_ + o] : 0.f;
#pragma unroll
            for (int c4 = 0; c4 < 4; c4++) {
                int kk = k + c4 * 4;
                float4 h0 = *(const float4*)(h2_s + (r0 + 0) * KP_ + kk);
                float4 h1 = *(const float4*)(h2_s + (r0 + 1) * KP_ + kk);
                float w0 = wc[c4 * 4 + 0], w1 = wc[c4 * 4 + 1];
                float w2 = wc[c4 * 4 + 2], w3 = wc[c4 * 4 + 3];
                a0 = fmaf(h0.x, w0, a0); a0 = fmaf(h0.y, w1, a0);
                a0 = fmaf(h0.z, w2, a0); a0 = fmaf(h0.w, w3, a0);
                a1 = fmaf(h1.x, w0, a1); a1 = fmaf(h1.y, w1, a1);
                a1 = fmaf(h1.z, w2, a1); a1 = fmaf(h1.w, w3, a1);
            }
#pragma unroll
            for (int u = 0; u < 16; u++) wc[u] = wn[u];
        }
        out[(row0 + r0 + 0) * KL_ + o] = a0;
        out[(row0 + r0 + 1) * KL_ + o] = a1;
    }
}

// ---------------------------------------------------------------------------
extern "C" void kernel_launch(void* const* d_in, const int* in_sizes, int n_in,
                              void* d_out, int out_size) {
    const float* x0    = (const float*)d_in[0];
    const float* x     = (const float*)d_in[1];
    const float* N     = (const float*)d_in[2];
    const float* basis = (const float*)d_in[3];
    const float* v     = (const float*)d_in[4];
    const float* W0    = (const float*)d_in[5];
    const float* b0    = (const float*)d_in[6];
    const float* W1    = (const float*)d_in[7];
    const float* b1    = (const float*)d_in[8];
    const float* W2    = (const float*)d_in[9];
    const float* b2    = (const float*)d_in[10];

    precomp_kernel<<<B_, HP_>>>(W0, b0, basis);
    main_kernel<<<B_ * NT_, 128>>>(x0, x, N, v);
    tail_kernel<<<(B_ * NT_) / ROWS2_, 256>>>(W1, b1, W2, b2, (float*)d_out);
}